// round 1
// baseline (speedup 1.0000x reference)
#include <cuda_runtime.h>
#include <math.h>

// Problem constants
constexpr int NN  = 16384;   // nodes
constexpr int DD  = 128;     // dim
constexpr int EE  = 262144;  // edges
constexpr int SEQ = 512;     // nodes per graph
constexpr int NGR = 32;      // graphs
constexpr int NH  = 8;       // heads (dh = 16)

// ---------------- scratch (no allocations allowed) ----------------
__device__ float g_z   [NN * DD];
__device__ float g_t1  [NN * 2 * DD];
__device__ float g_hl  [NN * DD];
__device__ float g_qkv [NN * 3 * DD];
__device__ float g_ao  [NN * DD];
__device__ float g_ha  [NN * DD];
__device__ float g_h   [NN * DD];
__device__ float g_h2  [NN * DD];
__device__ float g_stats[256];

// =====================================================================
// Edge kernel: z = x + segment_sum(relu(x[src] + edge_attr), dst)
// block = (graph g, 32-col chunk). Edges compacted into a smem queue
// (chunk size == queue capacity == 8192 -> overflow impossible), then
// drained warp-per-edge with smem atomics (bank-conflict-free: lane==col).
// =====================================================================
__global__ void __launch_bounds__(256)
edge_kernel(const float* __restrict__ x, const int* __restrict__ src,
            const int* __restrict__ dst, const float* __restrict__ ea,
            float* __restrict__ z)
{
    extern __shared__ float sm[];
    float* acc = sm;                   // 512 * 32 floats
    int*   q   = (int*)(sm + 512*32);  // 8192 ints
    __shared__ int qn;

    const int g  = blockIdx.x >> 2;
    const int c0 = (blockIdx.x & 3) * 32;
    const int tid = threadIdx.x;
    const int lane = tid & 31, warp = tid >> 5;

    for (int i = tid; i < 512*32; i += 256) acc[i] = 0.f;
    if (tid == 0) qn = 0;
    __syncthreads();

    for (int chunk = 0; chunk < EE; chunk += 8192) {
        // scan + compact
        for (int e = chunk + tid; e < chunk + 8192; e += 256) {
            int s = src[e];
            if ((s >> 9) == g) { int p = atomicAdd(&qn, 1); q[p] = e; }
        }
        __syncthreads();
        int n = qn;
        // drain: one warp per edge, lane = column
        for (int i = warp; i < n; i += 8) {
            int e = q[i];
            int s = src[e];
            int d = dst[e] & 511;
            float xv = __ldg(x  + (size_t)s * DD + c0 + lane);
            float ev = __ldg(ea + (size_t)e * DD + c0 + lane);
            float m = xv + ev;
            if (m > 0.f) atomicAdd(acc + d * 32 + lane, m);
        }
        __syncthreads();
        if (tid == 0) qn = 0;
        __syncthreads();
    }

    // z = x + aggr
    for (int i = tid; i < 512*32; i += 256) {
        int r = i >> 5, c = i & 31;
        size_t gi = (size_t)(g * SEQ + r) * DD + c0 + c;
        z[gi] = x[gi] + acc[i];
    }
}

// =====================================================================
// SIMT SGEMM: C[M,ncols] = act(A[M,K] * B + bias) (+ resid)
// 128x128 output tile per block, 256 threads, 8x8 micro-tile per thread.
// A is staged k-major in smem (conflict-free stores, broadcast reads).
// TRANSB: B stored [ncols, K] row-major (used for torch-style W.T matmuls).
// =====================================================================
template<int KCHUNKS, bool TRANSB, bool RELU, bool RESID>
__global__ void __launch_bounds__(256, 1)
gemm_kernel(const float* __restrict__ A, int lda,
            const float* __restrict__ B, int ldb,
            const float* __restrict__ bias,
            const float* __restrict__ resid,
            float* __restrict__ C, int ldc)
{
    extern __shared__ float sm[];
    float* As = sm;              // [128 k][128 m]
    float* Bs = sm + 128 * 128;  // [128 k][128 n]

    const int tid = threadIdx.x;
    const int tx = tid & 15, ty = tid >> 4;
    const int m0 = blockIdx.x * 128;
    const int n0 = blockIdx.y * 128;

    float acc[8][8];
#pragma unroll
    for (int i = 0; i < 8; ++i)
#pragma unroll
        for (int j = 0; j < 8; ++j) acc[i][j] = 0.f;

    for (int kc = 0; kc < KCHUNKS; ++kc) {
        if (kc) __syncthreads();
        // ---- stage A chunk (transpose to k-major) ----
#pragma unroll
        for (int it = 0; it < 16; ++it) {
            int idx = tid + it * 256;          // 0..4095 float4s
            int m = idx & 127, k4 = idx >> 7;  // lanes vary m -> coalesced STS
            float4 a = *(const float4*)(A + (size_t)(m0 + m) * lda + kc * 128 + k4 * 4);
            As[(k4*4+0)*128 + m] = a.x;
            As[(k4*4+1)*128 + m] = a.y;
            As[(k4*4+2)*128 + m] = a.z;
            As[(k4*4+3)*128 + m] = a.w;
        }
        // ---- stage B chunk ----
        if (TRANSB) {
#pragma unroll
            for (int it = 0; it < 16; ++it) {
                int idx = tid + it * 256;
                int n = idx & 127, k4 = idx >> 7;
                float4 b = *(const float4*)(B + (size_t)(n0 + n) * ldb + kc * 128 + k4 * 4);
                Bs[(k4*4+0)*128 + n] = b.x;
                Bs[(k4*4+1)*128 + n] = b.y;
                Bs[(k4*4+2)*128 + n] = b.z;
                Bs[(k4*4+3)*128 + n] = b.w;
            }
        } else {
#pragma unroll
            for (int it = 0; it < 16; ++it) {
                int idx = tid + it * 256;
                int n4 = idx & 31, k = idx >> 5;
                float4 b = *(const float4*)(B + (size_t)(kc * 128 + k) * ldb + n0 + n4 * 4);
                *(float4*)(Bs + k * 128 + n4 * 4) = b;
            }
        }
        __syncthreads();

        const float* ap = As + ty * 8;
        const float* bp = Bs + tx * 8;
#pragma unroll 4
        for (int k = 0; k < 128; ++k) {
            float4 a0 = *(const float4*)(ap + k * 128);
            float4 a1 = *(const float4*)(ap + k * 128 + 4);
            float4 b0 = *(const float4*)(bp + k * 128);
            float4 b1 = *(const float4*)(bp + k * 128 + 4);
            float av[8] = {a0.x, a0.y, a0.z, a0.w, a1.x, a1.y, a1.z, a1.w};
            float bv[8] = {b0.x, b0.y, b0.z, b0.w, b1.x, b1.y, b1.z, b1.w};
#pragma unroll
            for (int i = 0; i < 8; ++i)
#pragma unroll
                for (int j = 0; j < 8; ++j)
                    acc[i][j] = fmaf(av[i], bv[j], acc[i][j]);
        }
    }

    // ---- epilogue ----
    float4 bb0 = *(const float4*)(bias + n0 + tx * 8);
    float4 bb1 = *(const float4*)(bias + n0 + tx * 8 + 4);
    float bvec[8] = {bb0.x, bb0.y, bb0.z, bb0.w, bb1.x, bb1.y, bb1.z, bb1.w};

#pragma unroll
    for (int i = 0; i < 8; ++i) {
        int row = m0 + ty * 8 + i;
        float o[8];
#pragma unroll
        for (int j = 0; j < 8; ++j) {
            float v = acc[i][j] + bvec[j];
            if (RELU) v = fmaxf(v, 0.f);
            o[j] = v;
        }
        if (RESID) {
            float4 r0 = *(const float4*)(resid + (size_t)row * ldc + n0 + tx * 8);
            float4 r1 = *(const float4*)(resid + (size_t)row * ldc + n0 + tx * 8 + 4);
            o[0]+=r0.x; o[1]+=r0.y; o[2]+=r0.z; o[3]+=r0.w;
            o[4]+=r1.x; o[5]+=r1.y; o[6]+=r1.z; o[7]+=r1.w;
        }
        float* cp = C + (size_t)row * ldc + n0 + tx * 8;
        *(float4*)cp       = make_float4(o[0], o[1], o[2], o[3]);
        *(float4*)(cp + 4) = make_float4(o[4], o[5], o[6], o[7]);
    }
}

// =====================================================================
// Attention: one block per (graph, head). K,V tiles [512,16] in smem.
// Each thread owns 2 q rows; streaming exp-weighted accumulation
// (scores bounded -> no max subtraction needed; mathematically equal).
// =====================================================================
__device__ __forceinline__ float dot4(float4 a, float4 b) {
    return fmaf(a.x, b.x, fmaf(a.y, b.y, fmaf(a.z, b.z, a.w * b.w)));
}
__device__ __forceinline__ void fma4(float4& o, float p, float4 v) {
    o.x = fmaf(p, v.x, o.x); o.y = fmaf(p, v.y, o.y);
    o.z = fmaf(p, v.z, o.z); o.w = fmaf(p, v.w, o.w);
}

__global__ void __launch_bounds__(256, 2)
attn_kernel(const float* __restrict__ qkv, float* __restrict__ ao)
{
    extern __shared__ float sm[];
    float* Ks = sm;             // [512][16]
    float* Vs = sm + 512 * 16;  // [512][16]

    const int g = blockIdx.x >> 3, h = blockIdx.x & 7;
    const float* base = qkv + (size_t)g * SEQ * 384;
    const int tid = threadIdx.x;

    for (int idx = tid; idx < 2048; idx += 256) {
        int r = idx >> 2, c = (idx & 3) * 4;
        *(float4*)(Ks + r * 16 + c) = *(const float4*)(base + (size_t)r * 384 + 128 + h * 16 + c);
        *(float4*)(Vs + r * 16 + c) = *(const float4*)(base + (size_t)r * 384 + 256 + h * 16 + c);
    }

    const int r0 = tid * 2;
    const float* q0p = base + (size_t)r0 * 384 + h * 16;
    const float* q1p = q0p + 384;
    float4 q0a = *(const float4*)(q0p),     q0b = *(const float4*)(q0p + 4);
    float4 q0c = *(const float4*)(q0p + 8), q0d = *(const float4*)(q0p + 12);
    float4 q1a = *(const float4*)(q1p),     q1b = *(const float4*)(q1p + 4);
    float4 q1c = *(const float4*)(q1p + 8), q1d = *(const float4*)(q1p + 12);
    __syncthreads();

    float4 o0a = {0,0,0,0}, o0b = {0,0,0,0}, o0c = {0,0,0,0}, o0d = {0,0,0,0};
    float4 o1a = {0,0,0,0}, o1b = {0,0,0,0}, o1c = {0,0,0,0}, o1d = {0,0,0,0};
    float l0 = 0.f, l1 = 0.f;

#pragma unroll 2
    for (int k = 0; k < SEQ; ++k) {
        const float* kr = Ks + k * 16;
        float4 ka = *(const float4*)(kr),     kb = *(const float4*)(kr + 4);
        float4 kc4 = *(const float4*)(kr + 8), kd = *(const float4*)(kr + 12);
        float s0 = dot4(q0a, ka) + dot4(q0b, kb) + dot4(q0c, kc4) + dot4(q0d, kd);
        float s1 = dot4(q1a, ka) + dot4(q1b, kb) + dot4(q1c, kc4) + dot4(q1d, kd);
        float p0 = __expf(s0 * 0.25f);   // 1/sqrt(dh)=0.25
        float p1 = __expf(s1 * 0.25f);
        l0 += p0; l1 += p1;
        const float* vr = Vs + k * 16;
        float4 va = *(const float4*)(vr),     vb = *(const float4*)(vr + 4);
        float4 vc = *(const float4*)(vr + 8), vd = *(const float4*)(vr + 12);
        fma4(o0a, p0, va); fma4(o0b, p0, vb); fma4(o0c, p0, vc); fma4(o0d, p0, vd);
        fma4(o1a, p1, va); fma4(o1b, p1, vb); fma4(o1c, p1, vc); fma4(o1d, p1, vd);
    }

    float i0 = 1.f / l0, i1 = 1.f / l1;
    float* op0 = ao + (size_t)(g * SEQ + r0) * DD + h * 16;
    float* op1 = op0 + DD;
    *(float4*)(op0)      = make_float4(o0a.x*i0, o0a.y*i0, o0a.z*i0, o0a.w*i0);
    *(float4*)(op0 + 4)  = make_float4(o0b.x*i0, o0b.y*i0, o0b.z*i0, o0b.w*i0);
    *(float4*)(op0 + 8)  = make_float4(o0c.x*i0, o0c.y*i0, o0c.z*i0, o0c.w*i0);
    *(float4*)(op0 + 12) = make_float4(o0d.x*i0, o0d.y*i0, o0d.z*i0, o0d.w*i0);
    *(float4*)(op1)      = make_float4(o1a.x*i1, o1a.y*i1, o1a.z*i1, o1a.w*i1);
    *(float4*)(op1 + 4)  = make_float4(o1b.x*i1, o1b.y*i1, o1b.z*i1, o1b.w*i1);
    *(float4*)(op1 + 8)  = make_float4(o1c.x*i1, o1c.y*i1, o1c.z*i1, o1c.w*i1);
    *(float4*)(op1 + 12) = make_float4(o1d.x*i1, o1d.y*i1, o1d.z*i1, o1d.w*i1);
}

// =====================================================================
// BatchNorm (training-mode stats, biased var)
// =====================================================================
__global__ void zero_stats(float* stats) { stats[threadIdx.x] = 0.f; }

__global__ void __launch_bounds__(256)
bn_stats(const float* __restrict__ X, float* __restrict__ stats)
{
    int col = threadIdx.x & 127;
    int half = threadIdx.x >> 7;
    int row0 = blockIdx.x * 128 + half * 64;
    const float* p = X + (size_t)row0 * DD + col;
    float s = 0.f, s2 = 0.f;
#pragma unroll 8
    for (int r = 0; r < 64; ++r) {
        float v = p[r * DD];
        s += v; s2 = fmaf(v, v, s2);
    }
    atomicAdd(stats + col, s);
    atomicAdd(stats + 128 + col, s2);
}

template<bool ADD>
__global__ void __launch_bounds__(256)
bn_apply(const float* __restrict__ X, const float* __restrict__ stats,
         const float* __restrict__ gamma, const float* __restrict__ beta,
         const float* __restrict__ addend, float* __restrict__ out)
{
    int col = threadIdx.x & 127;
    int half = threadIdx.x >> 7;
    float mean = stats[col] * (1.f / (float)NN);
    float var  = stats[128 + col] * (1.f / (float)NN) - mean * mean;
    float sc = gamma[col] * rsqrtf(var + 1e-5f);
    float sh = beta[col] - mean * sc;
    int row0 = blockIdx.x * 128 + half * 64;
    size_t off = (size_t)row0 * DD + col;
#pragma unroll 4
    for (int r = 0; r < 64; ++r) {
        float v = X[off + r * DD] * sc + sh;
        if (ADD) v += addend[off + r * DD];
        out[off + r * DD] = v;
    }
}

// =====================================================================
// Host launcher
// =====================================================================
static void set_attrs()
{
    cudaFuncSetAttribute(edge_kernel, cudaFuncAttributeMaxDynamicSharedMemorySize, 98304);
    cudaFuncSetAttribute(attn_kernel, cudaFuncAttributeMaxDynamicSharedMemorySize, 65536);
    cudaFuncSetAttribute(gemm_kernel<1, false, true,  false>, cudaFuncAttributeMaxDynamicSharedMemorySize, 131072);
    cudaFuncSetAttribute(gemm_kernel<1, false, false, true >, cudaFuncAttributeMaxDynamicSharedMemorySize, 131072);
    cudaFuncSetAttribute(gemm_kernel<1, true,  false, false>, cudaFuncAttributeMaxDynamicSharedMemorySize, 131072);
    cudaFuncSetAttribute(gemm_kernel<1, true,  false, true >, cudaFuncAttributeMaxDynamicSharedMemorySize, 131072);
    cudaFuncSetAttribute(gemm_kernel<2, false, false, true >, cudaFuncAttributeMaxDynamicSharedMemorySize, 131072);
}

extern "C" void kernel_launch(void* const* d_in, const int* in_sizes, int n_in,
                              void* d_out, int out_size)
{
    const float* x          = (const float*)d_in[0];
    const int*   edge_index = (const int*)  d_in[1];
    const float* edge_attr  = (const float*)d_in[2];
    const float* gin_w1     = (const float*)d_in[3];
    const float* gin_b1     = (const float*)d_in[4];
    const float* gin_w2     = (const float*)d_in[5];
    const float* gin_b2     = (const float*)d_in[6];
    const float* bn1l_g     = (const float*)d_in[7];
    const float* bn1l_b     = (const float*)d_in[8];
    const float* in_proj_w  = (const float*)d_in[9];
    const float* in_proj_b  = (const float*)d_in[10];
    const float* out_proj_w = (const float*)d_in[11];
    const float* out_proj_b = (const float*)d_in[12];
    const float* bn1a_g     = (const float*)d_in[13];
    const float* bn1a_b     = (const float*)d_in[14];
    const float* ff_w1      = (const float*)d_in[15];
    const float* ff_b1      = (const float*)d_in[16];
    const float* ff_w2      = (const float*)d_in[17];
    const float* ff_b2      = (const float*)d_in[18];
    const float* bn2_g      = (const float*)d_in[19];
    const float* bn2_b      = (const float*)d_in[20];
    float* out = (float*)d_out;

    set_attrs();

    float *z, *t1, *hl, *qkvb, *ao, *ha, *h, *h2, *stats;
    cudaGetSymbolAddress((void**)&z,    g_z);
    cudaGetSymbolAddress((void**)&t1,   g_t1);
    cudaGetSymbolAddress((void**)&hl,   g_hl);
    cudaGetSymbolAddress((void**)&qkvb, g_qkv);
    cudaGetSymbolAddress((void**)&ao,   g_ao);
    cudaGetSymbolAddress((void**)&ha,   g_ha);
    cudaGetSymbolAddress((void**)&h,    g_h);
    cudaGetSymbolAddress((void**)&h2,   g_h2);
    cudaGetSymbolAddress((void**)&stats, g_stats);

    const int* src = edge_index;
    const int* dst = edge_index + EE;
    const dim3 blk(256);
    const int GB = NN / 128;  // 128 M-tiles

    // ---- local GINE branch ----
    edge_kernel<<<128, blk, 98304>>>(x, src, dst, edge_attr, z);
    gemm_kernel<1, false, true,  false><<<dim3(GB, 1), blk, 131072>>>(z,  DD, gin_w1, DD, gin_b1, nullptr, t1, DD);
    gemm_kernel<1, false, false, true ><<<dim3(GB, 1), blk, 131072>>>(t1, DD, gin_w2, DD, gin_b2, x,       hl, DD);
    zero_stats<<<1, 256>>>(stats);
    bn_stats<<<128, blk>>>(hl, stats);
    bn_apply<false><<<128, blk>>>(hl, stats, bn1l_g, bn1l_b, nullptr, hl);

    // ---- global attention branch ----
    gemm_kernel<1, true, false, false><<<dim3(GB, 3), blk, 131072>>>(x, DD, in_proj_w, DD, in_proj_b, nullptr, qkvb, 384);
    attn_kernel<<<NGR * NH, blk, 65536>>>(qkvb, ao);
    gemm_kernel<1, true, false, true ><<<dim3(GB, 1), blk, 131072>>>(ao, DD, out_proj_w, DD, out_proj_b, x, ha, DD);
    zero_stats<<<1, 256>>>(stats);
    bn_stats<<<128, blk>>>(ha, stats);
    bn_apply<true><<<128, blk>>>(ha, stats, bn1a_g, bn1a_b, hl, h);  // h = bn(ha) + h_local

    // ---- FFN ----
    gemm_kernel<1, false, true,  false><<<dim3(GB, 2), blk, 131072>>>(h,  DD,      ff_w1, 2 * DD, ff_b1, nullptr, t1, 2 * DD);
    gemm_kernel<2, false, false, true ><<<dim3(GB, 1), blk, 131072>>>(t1, 2 * DD,  ff_w2, DD,     ff_b2, h,       h2, DD);
    zero_stats<<<1, 256>>>(stats);
    bn_stats<<<128, blk>>>(h2, stats);
    bn_apply<false><<<128, blk>>>(h2, stats, bn2_g, bn2_b, nullptr, out);
}

// round 2
// speedup vs baseline: 3.7817x; 3.7817x over previous
#include <cuda_runtime.h>
#include <math.h>
#include <stdint.h>

// Problem constants
constexpr int NN  = 16384;   // nodes
constexpr int DD  = 128;     // dim
constexpr int EE  = 262144;  // edges
constexpr int SEQ = 512;     // nodes per graph
constexpr int NGR = 32;      // graphs
constexpr int NH  = 8;       // heads (dh = 16)

// ---------------- scratch (no allocations allowed) ----------------
__device__ float g_z   [NN * DD];
__device__ float g_t1  [NN * 2 * DD];
__device__ float g_hl  [NN * DD];
__device__ float g_qkv [NN * 3 * DD];
__device__ float g_ao  [NN * DD];
__device__ float g_ha  [NN * DD];
__device__ float g_h   [NN * DD];
__device__ float g_h2  [NN * DD];
__device__ float g_stats[256];
__device__ int   g_deg [NN];
__device__ int   g_off [NN + 1];
__device__ int   g_pos [NN];
__device__ int   g_eid [EE];

// =====================================================================
// CSR build by dst:  count -> scan -> scatter
// =====================================================================
__global__ void zero_deg(int* deg) { deg[blockIdx.x * 256 + threadIdx.x] = 0; }

__global__ void count_kernel(const int* __restrict__ dst, int* __restrict__ deg)
{
    int e = blockIdx.x * 256 + threadIdx.x;
    atomicAdd(&deg[dst[e]], 1);
}

__global__ void __launch_bounds__(1024)
scan_kernel(const int* __restrict__ deg, int* __restrict__ off, int* __restrict__ pos)
{
    __shared__ int buf[2][1024];
    int t = threadIdx.x;
    int base = t * 16;
    int loc[16];
    int sum = 0;
#pragma unroll
    for (int i = 0; i < 16; ++i) { loc[i] = sum; sum += deg[base + i]; }
    buf[0][t] = sum;
    __syncthreads();
    int sel = 0;
    for (int d = 1; d < 1024; d <<= 1) {
        int v = buf[sel][t] + (t >= d ? buf[sel][t - d] : 0);
        buf[sel ^ 1][t] = v;
        sel ^= 1;
        __syncthreads();
    }
    int excl = buf[sel][t] - sum;
#pragma unroll
    for (int i = 0; i < 16; ++i) {
        int o = excl + loc[i];
        off[base + i] = o;
        pos[base + i] = o;
    }
    if (t == 1023) off[NN] = excl + sum;
}

__global__ void scatter_kernel(const int* __restrict__ dst, int* __restrict__ pos,
                               int* __restrict__ eid)
{
    int e = blockIdx.x * 256 + threadIdx.x;
    int p = atomicAdd(&pos[dst[e]], 1);
    eid[p] = e;
}

// =====================================================================
// Gather aggregation (no atomics): warp per dst node, lane = float4 col.
// z = x + sum_{e -> node} relu(x[src[e]] + ea[e])
// =====================================================================
__global__ void __launch_bounds__(256)
aggr_kernel(const float* __restrict__ x, const int* __restrict__ src,
            const float* __restrict__ ea, const int* __restrict__ off,
            const int* __restrict__ eid, float* __restrict__ z)
{
    int node = blockIdx.x * 8 + (threadIdx.x >> 5);
    int lane = threadIdx.x & 31;
    int beg = off[node], end = off[node + 1];
    const float4* x4  = (const float4*)x;
    const float4* ea4 = (const float4*)ea;
    float4 acc = make_float4(0.f, 0.f, 0.f, 0.f);
#pragma unroll 2
    for (int i = beg; i < end; ++i) {
        int e = __ldg(eid + i);
        int s = __ldg(src + e);
        float4 a = x4[(size_t)s * 32 + lane];
        float4 b = ea4[(size_t)e * 32 + lane];
        acc.x += fmaxf(a.x + b.x, 0.f);
        acc.y += fmaxf(a.y + b.y, 0.f);
        acc.z += fmaxf(a.z + b.z, 0.f);
        acc.w += fmaxf(a.w + b.w, 0.f);
    }
    float4 xv = x4[(size_t)node * 32 + lane];
    ((float4*)z)[(size_t)node * 32 + lane] =
        make_float4(xv.x + acc.x, xv.y + acc.y, xv.z + acc.z, xv.w + acc.w);
}

// =====================================================================
// TF32 tensor-core GEMM: C = act(A[M,K] * B + bias) (+ resid)
// Block tile 128x128, 8 warps in 2(m)x4(n), warp tile 64x32.
// mma.sync.aligned.m16n8k8.row.col.f32.tf32.tf32.f32
// =====================================================================
__device__ __forceinline__ uint32_t to_tf32(float f)
{
    uint32_t u;
    asm("cvt.rna.tf32.f32 %0, %1;" : "=r"(u) : "f"(f));
    return u;
}

__device__ __forceinline__ void mma_tf32(float c[4], const uint32_t a[4], const uint32_t b[2])
{
    asm volatile(
        "mma.sync.aligned.m16n8k8.row.col.f32.tf32.tf32.f32 "
        "{%0,%1,%2,%3}, {%4,%5,%6,%7}, {%8,%9}, {%0,%1,%2,%3};\n"
        : "+f"(c[0]), "+f"(c[1]), "+f"(c[2]), "+f"(c[3])
        : "r"(a[0]), "r"(a[1]), "r"(a[2]), "r"(a[3]), "r"(b[0]), "r"(b[1]));
}

template<bool TRANSB, bool RELU, bool RESID>
__global__ void __launch_bounds__(256)
gemm_tf32(const float* __restrict__ A, int Ktot,
          const float* __restrict__ B, int ldb,
          const float* __restrict__ bias,
          const float* __restrict__ resid,
          float* __restrict__ C, int ldc)
{
    __shared__ uint32_t As[128 * 20];  // [m][k], stride 20 (pad for frag loads)
    __shared__ uint32_t Bs[128 * 20];  // [n][k]

    const int tid = threadIdx.x;
    const int lane = tid & 31;
    const int warp = tid >> 5;
    const int wm = warp >> 2;          // 0..1
    const int wn = warp & 3;           // 0..3
    const int g = lane >> 2;           // 0..7
    const int tig = lane & 3;          // 0..3
    const int m0 = blockIdx.x * 128;
    const int n0 = blockIdx.y * 128;

    float c[4][4][4];
#pragma unroll
    for (int i = 0; i < 4; ++i)
#pragma unroll
        for (int j = 0; j < 4; ++j)
#pragma unroll
            for (int r = 0; r < 4; ++r) c[i][j][r] = 0.f;

    const int nkt = Ktot >> 4;
    for (int kt = 0; kt < nkt; ++kt) {
        if (kt) __syncthreads();
        // ---- A tile: [128 rows][16 k] -> As[m][k] ----
#pragma unroll
        for (int it = 0; it < 2; ++it) {
            int idx = tid + it * 256;
            int r = idx >> 2, k4 = (idx & 3) * 4;
            float4 v = *(const float4*)(A + (size_t)(m0 + r) * Ktot + kt * 16 + k4);
            uint32_t* d = As + r * 20 + k4;
            d[0] = to_tf32(v.x); d[1] = to_tf32(v.y);
            d[2] = to_tf32(v.z); d[3] = to_tf32(v.w);
        }
        // ---- B tile -> Bs[n][k] ----
        if (TRANSB) {
#pragma unroll
            for (int it = 0; it < 2; ++it) {
                int idx = tid + it * 256;
                int r = idx >> 2, k4 = (idx & 3) * 4;
                float4 v = *(const float4*)(B + (size_t)(n0 + r) * ldb + kt * 16 + k4);
                uint32_t* d = Bs + r * 20 + k4;
                d[0] = to_tf32(v.x); d[1] = to_tf32(v.y);
                d[2] = to_tf32(v.z); d[3] = to_tf32(v.w);
            }
        } else {
#pragma unroll
            for (int it = 0; it < 8; ++it) {
                int idx = tid + it * 256;
                int k = idx >> 7, n = idx & 127;
                Bs[n * 20 + k] = to_tf32(B[(size_t)(kt * 16 + k) * ldb + n0 + n]);
            }
        }
        __syncthreads();

#pragma unroll
        for (int k8 = 0; k8 < 16; k8 += 8) {
            uint32_t af[4][4];
#pragma unroll
            for (int mf = 0; mf < 4; ++mf) {
                const uint32_t* pa = As + (wm * 64 + mf * 16 + g) * 20 + k8 + tig;
                af[mf][0] = pa[0];
                af[mf][1] = pa[8 * 20];
                af[mf][2] = pa[4];
                af[mf][3] = pa[8 * 20 + 4];
            }
            uint32_t bf[4][2];
#pragma unroll
            for (int nf = 0; nf < 4; ++nf) {
                const uint32_t* pb = Bs + (wn * 32 + nf * 8 + g) * 20 + k8 + tig;
                bf[nf][0] = pb[0];
                bf[nf][1] = pb[4];
            }
#pragma unroll
            for (int mf = 0; mf < 4; ++mf)
#pragma unroll
                for (int nf = 0; nf < 4; ++nf)
                    mma_tf32(c[mf][nf], af[mf], bf[nf]);
        }
    }

    // ---- epilogue ----
#pragma unroll
    for (int mf = 0; mf < 4; ++mf) {
#pragma unroll
        for (int nf = 0; nf < 4; ++nf) {
            int row = m0 + wm * 64 + mf * 16 + g;
            int col = n0 + wn * 32 + nf * 8 + 2 * tig;
            float b0 = bias[col], b1 = bias[col + 1];
            float o00 = c[mf][nf][0] + b0, o01 = c[mf][nf][1] + b1;
            float o10 = c[mf][nf][2] + b0, o11 = c[mf][nf][3] + b1;
            if (RELU) {
                o00 = fmaxf(o00, 0.f); o01 = fmaxf(o01, 0.f);
                o10 = fmaxf(o10, 0.f); o11 = fmaxf(o11, 0.f);
            }
            if (RESID) {
                float2 r0 = *(const float2*)(resid + (size_t)row * ldc + col);
                float2 r1 = *(const float2*)(resid + (size_t)(row + 8) * ldc + col);
                o00 += r0.x; o01 += r0.y;
                o10 += r1.x; o11 += r1.y;
            }
            *(float2*)(C + (size_t)row * ldc + col)       = make_float2(o00, o01);
            *(float2*)(C + (size_t)(row + 8) * ldc + col) = make_float2(o10, o11);
        }
    }
}

// =====================================================================
// Attention: one block per (graph, head). K,V tiles [512,16] in smem.
// =====================================================================
__device__ __forceinline__ float dot4(float4 a, float4 b) {
    return fmaf(a.x, b.x, fmaf(a.y, b.y, fmaf(a.z, b.z, a.w * b.w)));
}
__device__ __forceinline__ void fma4(float4& o, float p, float4 v) {
    o.x = fmaf(p, v.x, o.x); o.y = fmaf(p, v.y, o.y);
    o.z = fmaf(p, v.z, o.z); o.w = fmaf(p, v.w, o.w);
}

__global__ void __launch_bounds__(256, 2)
attn_kernel(const float* __restrict__ qkv, float* __restrict__ ao)
{
    extern __shared__ float sm[];
    float* Ks = sm;             // [512][16]
    float* Vs = sm + 512 * 16;  // [512][16]

    const int g = blockIdx.x >> 3, h = blockIdx.x & 7;
    const float* base = qkv + (size_t)g * SEQ * 384;
    const int tid = threadIdx.x;

    for (int idx = tid; idx < 2048; idx += 256) {
        int r = idx >> 2, c = (idx & 3) * 4;
        *(float4*)(Ks + r * 16 + c) = *(const float4*)(base + (size_t)r * 384 + 128 + h * 16 + c);
        *(float4*)(Vs + r * 16 + c) = *(const float4*)(base + (size_t)r * 384 + 256 + h * 16 + c);
    }

    const int r0 = tid * 2;
    const float* q0p = base + (size_t)r0 * 384 + h * 16;
    const float* q1p = q0p + 384;
    float4 q0a = *(const float4*)(q0p),     q0b = *(const float4*)(q0p + 4);
    float4 q0c = *(const float4*)(q0p + 8), q0d = *(const float4*)(q0p + 12);
    float4 q1a = *(const float4*)(q1p),     q1b = *(const float4*)(q1p + 4);
    float4 q1c = *(const float4*)(q1p + 8), q1d = *(const float4*)(q1p + 12);
    __syncthreads();

    float4 o0a = {0,0,0,0}, o0b = {0,0,0,0}, o0c = {0,0,0,0}, o0d = {0,0,0,0};
    float4 o1a = {0,0,0,0}, o1b = {0,0,0,0}, o1c = {0,0,0,0}, o1d = {0,0,0,0};
    float l0 = 0.f, l1 = 0.f;

#pragma unroll 2
    for (int k = 0; k < SEQ; ++k) {
        const float* kr = Ks + k * 16;
        float4 ka = *(const float4*)(kr),      kb = *(const float4*)(kr + 4);
        float4 kc4 = *(const float4*)(kr + 8), kd = *(const float4*)(kr + 12);
        float s0 = dot4(q0a, ka) + dot4(q0b, kb) + dot4(q0c, kc4) + dot4(q0d, kd);
        float s1 = dot4(q1a, ka) + dot4(q1b, kb) + dot4(q1c, kc4) + dot4(q1d, kd);
        float p0 = __expf(s0 * 0.25f);
        float p1 = __expf(s1 * 0.25f);
        l0 += p0; l1 += p1;
        const float* vr = Vs + k * 16;
        float4 va = *(const float4*)(vr),      vb = *(const float4*)(vr + 4);
        float4 vc = *(const float4*)(vr + 8),  vd = *(const float4*)(vr + 12);
        fma4(o0a, p0, va); fma4(o0b, p0, vb); fma4(o0c, p0, vc); fma4(o0d, p0, vd);
        fma4(o1a, p1, va); fma4(o1b, p1, vb); fma4(o1c, p1, vc); fma4(o1d, p1, vd);
    }

    float i0 = 1.f / l0, i1 = 1.f / l1;
    float* op0 = ao + (size_t)(g * SEQ + r0) * DD + h * 16;
    float* op1 = op0 + DD;
    *(float4*)(op0)      = make_float4(o0a.x*i0, o0a.y*i0, o0a.z*i0, o0a.w*i0);
    *(float4*)(op0 + 4)  = make_float4(o0b.x*i0, o0b.y*i0, o0b.z*i0, o0b.w*i0);
    *(float4*)(op0 + 8)  = make_float4(o0c.x*i0, o0c.y*i0, o0c.z*i0, o0c.w*i0);
    *(float4*)(op0 + 12) = make_float4(o0d.x*i0, o0d.y*i0, o0d.z*i0, o0d.w*i0);
    *(float4*)(op1)      = make_float4(o1a.x*i1, o1a.y*i1, o1a.z*i1, o1a.w*i1);
    *(float4*)(op1 + 4)  = make_float4(o1b.x*i1, o1b.y*i1, o1b.z*i1, o1b.w*i1);
    *(float4*)(op1 + 8)  = make_float4(o1c.x*i1, o1c.y*i1, o1c.z*i1, o1c.w*i1);
    *(float4*)(op1 + 12) = make_float4(o1d.x*i1, o1d.y*i1, o1d.z*i1, o1d.w*i1);
}

// =====================================================================
// BatchNorm (training-mode stats, biased var)
// =====================================================================
__global__ void zero_stats(float* stats) { stats[threadIdx.x] = 0.f; }

__global__ void __launch_bounds__(256)
bn_stats(const float* __restrict__ X, float* __restrict__ stats)
{
    int col = threadIdx.x & 127;
    int half = threadIdx.x >> 7;
    int row0 = blockIdx.x * 128 + half * 64;
    const float* p = X + (size_t)row0 * DD + col;
    float s = 0.f, s2 = 0.f;
#pragma unroll 8
    for (int r = 0; r < 64; ++r) {
        float v = p[r * DD];
        s += v; s2 = fmaf(v, v, s2);
    }
    atomicAdd(stats + col, s);
    atomicAdd(stats + 128 + col, s2);
}

template<bool ADD>
__global__ void __launch_bounds__(256)
bn_apply(const float* __restrict__ X, const float* __restrict__ stats,
         const float* __restrict__ gamma, const float* __restrict__ beta,
         const float* __restrict__ addend, float* __restrict__ out)
{
    int col = threadIdx.x & 127;
    int half = threadIdx.x >> 7;
    float mean = stats[col] * (1.f / (float)NN);
    float var  = stats[128 + col] * (1.f / (float)NN) - mean * mean;
    float sc = gamma[col] * rsqrtf(var + 1e-5f);
    float sh = beta[col] - mean * sc;
    int row0 = blockIdx.x * 128 + half * 64;
    size_t off = (size_t)row0 * DD + col;
#pragma unroll 4
    for (int r = 0; r < 64; ++r) {
        float v = X[off + r * DD] * sc + sh;
        if (ADD) v += addend[off + r * DD];
        out[off + r * DD] = v;
    }
}

// =====================================================================
// Host launcher
// =====================================================================
extern "C" void kernel_launch(void* const* d_in, const int* in_sizes, int n_in,
                              void* d_out, int out_size)
{
    const float* x          = (const float*)d_in[0];
    const int*   edge_index = (const int*)  d_in[1];
    const float* edge_attr  = (const float*)d_in[2];
    const float* gin_w1     = (const float*)d_in[3];
    const float* gin_b1     = (const float*)d_in[4];
    const float* gin_w2     = (const float*)d_in[5];
    const float* gin_b2     = (const float*)d_in[6];
    const float* bn1l_g     = (const float*)d_in[7];
    const float* bn1l_b     = (const float*)d_in[8];
    const float* in_proj_w  = (const float*)d_in[9];
    const float* in_proj_b  = (const float*)d_in[10];
    const float* out_proj_w = (const float*)d_in[11];
    const float* out_proj_b = (const float*)d_in[12];
    const float* bn1a_g     = (const float*)d_in[13];
    const float* bn1a_b     = (const float*)d_in[14];
    const float* ff_w1      = (const float*)d_in[15];
    const float* ff_b1      = (const float*)d_in[16];
    const float* ff_w2      = (const float*)d_in[17];
    const float* ff_b2      = (const float*)d_in[18];
    const float* bn2_g      = (const float*)d_in[19];
    const float* bn2_b      = (const float*)d_in[20];
    float* out = (float*)d_out;

    cudaFuncSetAttribute(attn_kernel, cudaFuncAttributeMaxDynamicSharedMemorySize, 65536);

    float *z, *t1, *hl, *qkvb, *ao, *ha, *h, *h2, *stats;
    int *deg, *off, *pos, *eid;
    cudaGetSymbolAddress((void**)&z,    g_z);
    cudaGetSymbolAddress((void**)&t1,   g_t1);
    cudaGetSymbolAddress((void**)&hl,   g_hl);
    cudaGetSymbolAddress((void**)&qkvb, g_qkv);
    cudaGetSymbolAddress((void**)&ao,   g_ao);
    cudaGetSymbolAddress((void**)&ha,   g_ha);
    cudaGetSymbolAddress((void**)&h,    g_h);
    cudaGetSymbolAddress((void**)&h2,   g_h2);
    cudaGetSymbolAddress((void**)&stats, g_stats);
    cudaGetSymbolAddress((void**)&deg,  g_deg);
    cudaGetSymbolAddress((void**)&off,  g_off);
    cudaGetSymbolAddress((void**)&pos,  g_pos);
    cudaGetSymbolAddress((void**)&eid,  g_eid);

    const int* src = edge_index;
    const int* dst = edge_index + EE;
    const dim3 blk(256);
    const int GB = NN / 128;  // 128 M-tiles

    // ---- CSR by dst + gather aggregation ----
    zero_deg<<<64, blk>>>(deg);
    count_kernel<<<EE / 256, blk>>>(dst, deg);
    scan_kernel<<<1, 1024>>>(deg, off, pos);
    scatter_kernel<<<EE / 256, blk>>>(dst, pos, eid);
    aggr_kernel<<<NN / 8, blk>>>(x, src, edge_attr, off, eid, z);

    // ---- local GINE branch ----
    gemm_tf32<false, true,  false><<<dim3(GB, 1), blk>>>(z,  DD, gin_w1, DD, gin_b1, nullptr, t1, DD);
    gemm_tf32<false, false, true ><<<dim3(GB, 1), blk>>>(t1, DD, gin_w2, DD, gin_b2, x,       hl, DD);
    zero_stats<<<1, 256>>>(stats);
    bn_stats<<<128, blk>>>(hl, stats);
    bn_apply<false><<<128, blk>>>(hl, stats, bn1l_g, bn1l_b, nullptr, hl);

    // ---- global attention branch ----
    gemm_tf32<true, false, false><<<dim3(GB, 3), blk>>>(x, DD, in_proj_w, DD, in_proj_b, nullptr, qkvb, 384);
    attn_kernel<<<NGR * NH, blk, 65536>>>(qkvb, ao);
    gemm_tf32<true, false, true ><<<dim3(GB, 1), blk>>>(ao, DD, out_proj_w, DD, out_proj_b, x, ha, DD);
    zero_stats<<<1, 256>>>(stats);
    bn_stats<<<128, blk>>>(ha, stats);
    bn_apply<true><<<128, blk>>>(ha, stats, bn1a_g, bn1a_b, hl, h);  // h = bn(ha) + h_local

    // ---- FFN ----
    gemm_tf32<false, true,  false><<<dim3(GB, 2), blk>>>(h,  DD,      ff_w1, 2 * DD, ff_b1, nullptr, t1, 2 * DD);
    gemm_tf32<false, false, true ><<<dim3(GB, 1), blk>>>(t1, 2 * DD,  ff_w2, DD,     ff_b2, h,       h2, DD);
    zero_stats<<<1, 256>>>(stats);
    bn_stats<<<128, blk>>>(h2, stats);
    bn_apply<false><<<128, blk>>>(h2, stats, bn2_g, bn2_b, nullptr, out);
}

// round 3
// speedup vs baseline: 4.5492x; 1.2030x over previous
#include <cuda_runtime.h>
#include <math.h>
#include <stdint.h>

// Problem constants
constexpr int NN  = 16384;   // nodes
constexpr int DD  = 128;     // dim
constexpr int EE  = 262144;  // edges
constexpr int SEQ = 512;     // nodes per graph
constexpr int NGR = 32;      // graphs
constexpr int NH  = 8;       // heads (dh = 16)

// ---------------- scratch ----------------
__device__ float g_z   [NN * DD];
__device__ float g_t1  [NN * 2 * DD];
__device__ float g_hl  [NN * DD];
__device__ float g_qkv [NN * 3 * DD];
__device__ float g_ao  [NN * DD];
__device__ float g_ha  [NN * DD];
__device__ float g_h   [NN * DD];
__device__ float g_h2  [NN * DD];
__device__ float g_stats[768];   // [0:256) hl, [256:512) ha, [512:768) h2
__device__ int   g_deg [NN];
__device__ int   g_off [NN + 1];
__device__ int   g_pos [NN];
__device__ int   g_eid [EE];

// =====================================================================
// zero scratch (deg + stats)
// =====================================================================
__global__ void zero_misc(int* deg, float* stats)
{
    int i = blockIdx.x * 256 + threadIdx.x;
    deg[i] = 0;
    if (i < 768) stats[i] = 0.f;
}

// =====================================================================
// CSR build by dst:  count -> scan -> scatter
// =====================================================================
__global__ void count_kernel(const int* __restrict__ dst, int* __restrict__ deg)
{
    int e = blockIdx.x * 256 + threadIdx.x;
    atomicAdd(&deg[dst[e]], 1);
}

__global__ void __launch_bounds__(1024)
scan_kernel(const int* __restrict__ deg, int* __restrict__ off, int* __restrict__ pos)
{
    __shared__ int buf[2][1024];
    int t = threadIdx.x;
    int base = t * 16;
    int loc[16];
    int sum = 0;
#pragma unroll
    for (int i = 0; i < 16; ++i) { loc[i] = sum; sum += deg[base + i]; }
    buf[0][t] = sum;
    __syncthreads();
    int sel = 0;
    for (int d = 1; d < 1024; d <<= 1) {
        int v = buf[sel][t] + (t >= d ? buf[sel][t - d] : 0);
        buf[sel ^ 1][t] = v;
        sel ^= 1;
        __syncthreads();
    }
    int excl = buf[sel][t] - sum;
#pragma unroll
    for (int i = 0; i < 16; ++i) {
        int o = excl + loc[i];
        off[base + i] = o;
        pos[base + i] = o;
    }
    if (t == 1023) off[NN] = excl + sum;
}

__global__ void scatter_kernel(const int* __restrict__ dst, int* __restrict__ pos,
                               int* __restrict__ eid)
{
    int e = blockIdx.x * 256 + threadIdx.x;
    int p = atomicAdd(&pos[dst[e]], 1);
    eid[p] = e;
}

// =====================================================================
// Gather aggregation: z = x + sum_{e -> node} relu(x[src[e]] + ea[e])
// =====================================================================
__global__ void __launch_bounds__(256)
aggr_kernel(const float* __restrict__ x, const int* __restrict__ src,
            const float* __restrict__ ea, const int* __restrict__ off,
            const int* __restrict__ eid, float* __restrict__ z)
{
    int node = blockIdx.x * 8 + (threadIdx.x >> 5);
    int lane = threadIdx.x & 31;
    int beg = off[node], end = off[node + 1];
    const float4* x4  = (const float4*)x;
    const float4* ea4 = (const float4*)ea;
    float4 acc = make_float4(0.f, 0.f, 0.f, 0.f);
#pragma unroll 2
    for (int i = beg; i < end; ++i) {
        int e = __ldg(eid + i);
        int s = __ldg(src + e);
        float4 a = x4[(size_t)s * 32 + lane];
        float4 b = ea4[(size_t)e * 32 + lane];
        acc.x += fmaxf(a.x + b.x, 0.f);
        acc.y += fmaxf(a.y + b.y, 0.f);
        acc.z += fmaxf(a.z + b.z, 0.f);
        acc.w += fmaxf(a.w + b.w, 0.f);
    }
    float4 xv = x4[(size_t)node * 32 + lane];
    ((float4*)z)[(size_t)node * 32 + lane] =
        make_float4(xv.x + acc.x, xv.y + acc.y, xv.z + acc.z, xv.w + acc.w);
}

// =====================================================================
// TF32 mma helpers
// =====================================================================
__device__ __forceinline__ uint32_t to_tf32(float f)
{
    uint32_t u;
    asm("cvt.rna.tf32.f32 %0, %1;" : "=r"(u) : "f"(f));
    return u;
}

__device__ __forceinline__ void mma_tf32(float c[4], const uint32_t a[4], const uint32_t b[2])
{
    asm volatile(
        "mma.sync.aligned.m16n8k8.row.col.f32.tf32.tf32.f32 "
        "{%0,%1,%2,%3}, {%4,%5,%6,%7}, {%8,%9}, {%0,%1,%2,%3};\n"
        : "+f"(c[0]), "+f"(c[1]), "+f"(c[2]), "+f"(c[3])
        : "r"(a[0]), "r"(a[1]), "r"(a[2]), "r"(a[3]), "r"(b[0]), "r"(b[1]));
}

// =====================================================================
// TF32 GEMM: C = act(A[M,K] * B + bias) (+ resid) (+ fused BN stats)
// =====================================================================
template<bool TRANSB, bool RELU, bool RESID, bool STATS>
__global__ void __launch_bounds__(256)
gemm_tf32(const float* __restrict__ A, int Ktot,
          const float* __restrict__ B, int ldb,
          const float* __restrict__ bias,
          const float* __restrict__ resid,
          float* __restrict__ C, int ldc,
          float* __restrict__ stats)
{
    __shared__ uint32_t As[128 * 20];
    __shared__ uint32_t Bs[128 * 20];

    const int tid = threadIdx.x;
    const int lane = tid & 31;
    const int warp = tid >> 5;
    const int wm = warp >> 2;
    const int wn = warp & 3;
    const int g = lane >> 2;
    const int tig = lane & 3;
    const int m0 = blockIdx.x * 128;
    const int n0 = blockIdx.y * 128;

    float c[4][4][4];
#pragma unroll
    for (int i = 0; i < 4; ++i)
#pragma unroll
        for (int j = 0; j < 4; ++j)
#pragma unroll
            for (int r = 0; r < 4; ++r) c[i][j][r] = 0.f;

    const int nkt = Ktot >> 4;
    for (int kt = 0; kt < nkt; ++kt) {
        if (kt) __syncthreads();
#pragma unroll
        for (int it = 0; it < 2; ++it) {
            int idx = tid + it * 256;
            int r = idx >> 2, k4 = (idx & 3) * 4;
            float4 v = *(const float4*)(A + (size_t)(m0 + r) * Ktot + kt * 16 + k4);
            uint32_t* d = As + r * 20 + k4;
            d[0] = to_tf32(v.x); d[1] = to_tf32(v.y);
            d[2] = to_tf32(v.z); d[3] = to_tf32(v.w);
        }
        if (TRANSB) {
#pragma unroll
            for (int it = 0; it < 2; ++it) {
                int idx = tid + it * 256;
                int r = idx >> 2, k4 = (idx & 3) * 4;
                float4 v = *(const float4*)(B + (size_t)(n0 + r) * ldb + kt * 16 + k4);
                uint32_t* d = Bs + r * 20 + k4;
                d[0] = to_tf32(v.x); d[1] = to_tf32(v.y);
                d[2] = to_tf32(v.z); d[3] = to_tf32(v.w);
            }
        } else {
#pragma unroll
            for (int it = 0; it < 8; ++it) {
                int idx = tid + it * 256;
                int k = idx >> 7, n = idx & 127;
                Bs[n * 20 + k] = to_tf32(B[(size_t)(kt * 16 + k) * ldb + n0 + n]);
            }
        }
        __syncthreads();

#pragma unroll
        for (int k8 = 0; k8 < 16; k8 += 8) {
            uint32_t af[4][4];
#pragma unroll
            for (int mf = 0; mf < 4; ++mf) {
                const uint32_t* pa = As + (wm * 64 + mf * 16 + g) * 20 + k8 + tig;
                af[mf][0] = pa[0];
                af[mf][1] = pa[8 * 20];
                af[mf][2] = pa[4];
                af[mf][3] = pa[8 * 20 + 4];
            }
            uint32_t bf[4][2];
#pragma unroll
            for (int nf = 0; nf < 4; ++nf) {
                const uint32_t* pb = Bs + (wn * 32 + nf * 8 + g) * 20 + k8 + tig;
                bf[nf][0] = pb[0];
                bf[nf][1] = pb[4];
            }
#pragma unroll
            for (int mf = 0; mf < 4; ++mf)
#pragma unroll
                for (int nf = 0; nf < 4; ++nf)
                    mma_tf32(c[mf][nf], af[mf], bf[nf]);
        }
    }

    // ---- epilogue ----
    float cs[8], cq[8];
    if (STATS) {
#pragma unroll
        for (int j = 0; j < 8; ++j) { cs[j] = 0.f; cq[j] = 0.f; }
    }

#pragma unroll
    for (int mf = 0; mf < 4; ++mf) {
#pragma unroll
        for (int nf = 0; nf < 4; ++nf) {
            int row = m0 + wm * 64 + mf * 16 + g;
            int col = n0 + wn * 32 + nf * 8 + 2 * tig;
            float b0 = bias[col], b1 = bias[col + 1];
            float o00 = c[mf][nf][0] + b0, o01 = c[mf][nf][1] + b1;
            float o10 = c[mf][nf][2] + b0, o11 = c[mf][nf][3] + b1;
            if (RELU) {
                o00 = fmaxf(o00, 0.f); o01 = fmaxf(o01, 0.f);
                o10 = fmaxf(o10, 0.f); o11 = fmaxf(o11, 0.f);
            }
            if (RESID) {
                float2 r0 = *(const float2*)(resid + (size_t)row * ldc + col);
                float2 r1 = *(const float2*)(resid + (size_t)(row + 8) * ldc + col);
                o00 += r0.x; o01 += r0.y;
                o10 += r1.x; o11 += r1.y;
            }
            if (STATS) {
                cs[nf*2]   += o00 + o10;
                cs[nf*2+1] += o01 + o11;
                cq[nf*2]   += o00*o00 + o10*o10;
                cq[nf*2+1] += o01*o01 + o11*o11;
            }
            *(float2*)(C + (size_t)row * ldc + col)       = make_float2(o00, o01);
            *(float2*)(C + (size_t)(row + 8) * ldc + col) = make_float2(o10, o11);
        }
    }

    if (STATS) {
        float* sst = (float*)As;   // reuse smem: 256 floats
        __syncthreads();
        sst[tid] = 0.f;
        __syncthreads();
#pragma unroll
        for (int j = 0; j < 8; ++j) {
            int col = wn * 32 + (j >> 1) * 8 + 2 * tig + (j & 1);
            atomicAdd(&sst[col],       cs[j]);
            atomicAdd(&sst[128 + col], cq[j]);
        }
        __syncthreads();
        atomicAdd(&stats[tid], sst[tid]);
    }
}

// =====================================================================
// Flash-style TF32 tensor-core attention.
// Block = (graph, head), 8 warps; warp owns 64 q rows.
// Scores bounded -> streaming exp accumulation, no max subtraction
// (matches reference softmax exactly up to fp rounding).
// =====================================================================
constexpr int KS_STRIDE = 20;   // conflict-free for S b-frags
constexpr int VS_STRIDE = 24;   // conflict-free for PV b-frags
constexpr int P_STRIDE  = 36;   // conflict-free for a-frags
constexpr int ATTN_SMEM = (512 * KS_STRIDE + 512 * VS_STRIDE + 8 * 64 * P_STRIDE) * 4;

__global__ void __launch_bounds__(256, 1)
attn_mma(const float* __restrict__ qkv, float* __restrict__ ao)
{
    extern __shared__ uint32_t sm[];
    uint32_t* Ks = sm;                        // [512][20] tf32
    uint32_t* Vs = sm + 512 * KS_STRIDE;      // [512][24] tf32
    uint32_t* Pa = Vs + 512 * VS_STRIDE;      // 8 x [64][36]

    const int tid  = threadIdx.x;
    const int lane = tid & 31;
    const int warp = tid >> 5;
    const int g    = lane >> 2;   // 0..7
    const int tig  = lane & 3;    // 0..3
    const int gi = blockIdx.x >> 3, h = blockIdx.x & 7;
    const float* base = qkv + (size_t)gi * SEQ * 384;

    uint32_t* Pw = Pa + warp * 64 * P_STRIDE;
    const int m0 = warp * 64;

    // ---- stage K, V (tf32, padded) ----
    for (int idx = tid; idx < 2048; idx += 256) {
        int r = idx >> 2, c4 = (idx & 3) * 4;
        float4 kv = *(const float4*)(base + (size_t)r * 384 + 128 + h * 16 + c4);
        float4 vv = *(const float4*)(base + (size_t)r * 384 + 256 + h * 16 + c4);
        uint32_t* kd = Ks + r * KS_STRIDE + c4;
        kd[0] = to_tf32(kv.x); kd[1] = to_tf32(kv.y);
        kd[2] = to_tf32(kv.z); kd[3] = to_tf32(kv.w);
        uint32_t* vd = Vs + r * VS_STRIDE + c4;
        vd[0] = to_tf32(vv.x); vd[1] = to_tf32(vv.y);
        vd[2] = to_tf32(vv.z); vd[3] = to_tf32(vv.w);
    }
    // ---- stage Q (raw fp32) into this warp's P buffer ----
#pragma unroll
    for (int i = 0; i < 8; ++i) {
        int idx = lane + i * 32;
        int r = idx >> 2, c4 = (idx & 3) * 4;
        float4 qv = *(const float4*)(base + (size_t)(m0 + r) * 384 + h * 16 + c4);
        *(float4*)((float*)Pw + r * P_STRIDE + c4) = qv;
    }
    __syncthreads();

    // ---- Q fragments (scale 0.25 = 1/sqrt(dh) folded in) ----
    uint32_t qa[4][2][4];
#pragma unroll
    for (int mt = 0; mt < 4; ++mt)
#pragma unroll
        for (int ks = 0; ks < 2; ++ks) {
            const float* p = (const float*)Pw + (mt * 16 + g) * P_STRIDE + ks * 8 + tig;
            qa[mt][ks][0] = to_tf32(p[0] * 0.25f);
            qa[mt][ks][1] = to_tf32(p[8 * P_STRIDE] * 0.25f);
            qa[mt][ks][2] = to_tf32(p[4] * 0.25f);
            qa[mt][ks][3] = to_tf32(p[8 * P_STRIDE + 4] * 0.25f);
        }
    __syncwarp();

    float o[4][2][4];
    float lrow[4][2];
#pragma unroll
    for (int mt = 0; mt < 4; ++mt) {
        lrow[mt][0] = 0.f; lrow[mt][1] = 0.f;
#pragma unroll
        for (int nt = 0; nt < 2; ++nt)
#pragma unroll
            for (int r = 0; r < 4; ++r) o[mt][nt][r] = 0.f;
    }

    for (int j = 0; j < 16; ++j) {      // kv chunk of 32
        const int n0 = j * 32;
        // B-frags for S (from K)
        uint32_t bk[4][2][2];
#pragma unroll
        for (int nt = 0; nt < 4; ++nt)
#pragma unroll
            for (int ks = 0; ks < 2; ++ks) {
                const uint32_t* p = Ks + (n0 + nt * 8 + g) * KS_STRIDE + ks * 8 + tig;
                bk[nt][ks][0] = p[0];
                bk[nt][ks][1] = p[4];
            }
        // S = Q @ K^T
        float c[4][4][4];
#pragma unroll
        for (int mt = 0; mt < 4; ++mt)
#pragma unroll
            for (int nt = 0; nt < 4; ++nt) {
#pragma unroll
                for (int r = 0; r < 4; ++r) c[mt][nt][r] = 0.f;
                mma_tf32(c[mt][nt], qa[mt][0], bk[nt][0]);
                mma_tf32(c[mt][nt], qa[mt][1], bk[nt][1]);
            }
        // exp + row-sum partials + store P (tf32) to smem
#pragma unroll
        for (int mt = 0; mt < 4; ++mt) {
#pragma unroll
            for (int nt = 0; nt < 4; ++nt) {
                float p0 = __expf(c[mt][nt][0]);
                float p1 = __expf(c[mt][nt][1]);
                float p2 = __expf(c[mt][nt][2]);
                float p3 = __expf(c[mt][nt][3]);
                lrow[mt][0] += p0 + p1;
                lrow[mt][1] += p2 + p3;
                uint32_t* d0 = Pw + (mt * 16 + g) * P_STRIDE + nt * 8 + 2 * tig;
                uint32_t* d1 = d0 + 8 * P_STRIDE;
                d0[0] = to_tf32(p0); d0[1] = to_tf32(p1);
                d1[0] = to_tf32(p2); d1[1] = to_tf32(p3);
            }
        }
        __syncwarp();
        // B-frags for PV (from V)
        uint32_t bv[4][2][2];
#pragma unroll
        for (int k2 = 0; k2 < 4; ++k2)
#pragma unroll
            for (int nt = 0; nt < 2; ++nt) {
                const uint32_t* p = Vs + (n0 + k2 * 8 + tig) * VS_STRIDE + nt * 8 + g;
                bv[k2][nt][0] = p[0];
                bv[k2][nt][1] = p[4 * VS_STRIDE];
            }
        // O += P @ V
#pragma unroll
        for (int mt = 0; mt < 4; ++mt) {
#pragma unroll
            for (int k2 = 0; k2 < 4; ++k2) {
                uint32_t pa[4];
                const uint32_t* pp = Pw + (mt * 16 + g) * P_STRIDE + k2 * 8 + tig;
                pa[0] = pp[0];
                pa[1] = pp[8 * P_STRIDE];
                pa[2] = pp[4];
                pa[3] = pp[8 * P_STRIDE + 4];
                mma_tf32(o[mt][0], pa, bv[k2][0]);
                mma_tf32(o[mt][1], pa, bv[k2][1]);
            }
        }
        __syncwarp();
    }

    // ---- normalize + write ----
#pragma unroll
    for (int mt = 0; mt < 4; ++mt) {
        float l0 = lrow[mt][0], l1 = lrow[mt][1];
        l0 += __shfl_xor_sync(0xffffffffu, l0, 1);
        l0 += __shfl_xor_sync(0xffffffffu, l0, 2);
        l1 += __shfl_xor_sync(0xffffffffu, l1, 1);
        l1 += __shfl_xor_sync(0xffffffffu, l1, 2);
        float i0 = 1.f / l0, i1 = 1.f / l1;
        int grow = gi * SEQ + m0 + mt * 16 + g;
#pragma unroll
        for (int nt = 0; nt < 2; ++nt) {
            int col = h * 16 + nt * 8 + 2 * tig;
            *(float2*)(ao + (size_t)grow * DD + col) =
                make_float2(o[mt][nt][0] * i0, o[mt][nt][1] * i0);
            *(float2*)(ao + (size_t)(grow + 8) * DD + col) =
                make_float2(o[mt][nt][2] * i1, o[mt][nt][3] * i1);
        }
    }
}

// =====================================================================
// BatchNorm applies (stats already accumulated in GEMM epilogues)
// =====================================================================
__device__ __forceinline__ void bn_coef(const float* stats, const float* gamma,
                                        const float* beta, int col,
                                        float& sc, float& sh)
{
    float mean = stats[col] * (1.f / (float)NN);
    float var  = stats[128 + col] * (1.f / (float)NN) - mean * mean;
    sc = gamma[col] * rsqrtf(var + 1e-5f);
    sh = beta[col] - mean * sc;
}

__global__ void __launch_bounds__(256)
bn_apply_one(const float* __restrict__ X, const float* __restrict__ stats,
             const float* __restrict__ gamma, const float* __restrict__ beta,
             float* __restrict__ out)
{
    int col = threadIdx.x & 127;
    int half = threadIdx.x >> 7;
    float sc, sh;
    bn_coef(stats, gamma, beta, col, sc, sh);
    int row0 = blockIdx.x * 128 + half * 64;
    size_t off = (size_t)row0 * DD + col;
#pragma unroll 4
    for (int r = 0; r < 64; ++r)
        out[off + r * DD] = X[off + r * DD] * sc + sh;
}

// h = bn1a(ha) + bn1l(hl)
__global__ void __launch_bounds__(256)
bn_apply_dual(const float* __restrict__ ha, const float* __restrict__ statsA,
              const float* __restrict__ ga, const float* __restrict__ ba,
              const float* __restrict__ hl, const float* __restrict__ statsL,
              const float* __restrict__ gl, const float* __restrict__ bl,
              float* __restrict__ out)
{
    int col = threadIdx.x & 127;
    int half = threadIdx.x >> 7;
    float scA, shA, scL, shL;
    bn_coef(statsA, ga, ba, col, scA, shA);
    bn_coef(statsL, gl, bl, col, scL, shL);
    int row0 = blockIdx.x * 128 + half * 64;
    size_t off = (size_t)row0 * DD + col;
#pragma unroll 4
    for (int r = 0; r < 64; ++r)
        out[off + r * DD] = ha[off + r * DD] * scA + shA
                          + hl[off + r * DD] * scL + shL;
}

// =====================================================================
// Host launcher
// =====================================================================
extern "C" void kernel_launch(void* const* d_in, const int* in_sizes, int n_in,
                              void* d_out, int out_size)
{
    const float* x          = (const float*)d_in[0];
    const int*   edge_index = (const int*)  d_in[1];
    const float* edge_attr  = (const float*)d_in[2];
    const float* gin_w1     = (const float*)d_in[3];
    const float* gin_b1     = (const float*)d_in[4];
    const float* gin_w2     = (const float*)d_in[5];
    const float* gin_b2     = (const float*)d_in[6];
    const float* bn1l_g     = (const float*)d_in[7];
    const float* bn1l_b     = (const float*)d_in[8];
    const float* in_proj_w  = (const float*)d_in[9];
    const float* in_proj_b  = (const float*)d_in[10];
    const float* out_proj_w = (const float*)d_in[11];
    const float* out_proj_b = (const float*)d_in[12];
    const float* bn1a_g     = (const float*)d_in[13];
    const float* bn1a_b     = (const float*)d_in[14];
    const float* ff_w1      = (const float*)d_in[15];
    const float* ff_b1      = (const float*)d_in[16];
    const float* ff_w2      = (const float*)d_in[17];
    const float* ff_b2      = (const float*)d_in[18];
    const float* bn2_g      = (const float*)d_in[19];
    const float* bn2_b      = (const float*)d_in[20];
    float* out = (float*)d_out;

    cudaFuncSetAttribute(attn_mma, cudaFuncAttributeMaxDynamicSharedMemorySize, ATTN_SMEM);

    float *z, *t1, *hl, *qkvb, *ao, *ha, *h, *h2, *stats;
    int *deg, *off, *pos, *eid;
    cudaGetSymbolAddress((void**)&z,    g_z);
    cudaGetSymbolAddress((void**)&t1,   g_t1);
    cudaGetSymbolAddress((void**)&hl,   g_hl);
    cudaGetSymbolAddress((void**)&qkvb, g_qkv);
    cudaGetSymbolAddress((void**)&ao,   g_ao);
    cudaGetSymbolAddress((void**)&ha,   g_ha);
    cudaGetSymbolAddress((void**)&h,    g_h);
    cudaGetSymbolAddress((void**)&h2,   g_h2);
    cudaGetSymbolAddress((void**)&stats, g_stats);
    cudaGetSymbolAddress((void**)&deg,  g_deg);
    cudaGetSymbolAddress((void**)&off,  g_off);
    cudaGetSymbolAddress((void**)&pos,  g_pos);
    cudaGetSymbolAddress((void**)&eid,  g_eid);

    const int* src = edge_index;
    const int* dst = edge_index + EE;
    const dim3 blk(256);
    const int GB = NN / 128;

    float* stats_hl = stats;
    float* stats_ha = stats + 256;
    float* stats_h2 = stats + 512;

    // ---- CSR + gather aggregation ----
    zero_misc<<<64, blk>>>(deg, stats);
    count_kernel<<<EE / 256, blk>>>(dst, deg);
    scan_kernel<<<1, 1024>>>(deg, off, pos);
    scatter_kernel<<<EE / 256, blk>>>(dst, pos, eid);
    aggr_kernel<<<NN / 8, blk>>>(x, src, edge_attr, off, eid, z);

    // ---- attention branch (QKV + attn) ----
    gemm_tf32<true, false, false, false><<<dim3(GB, 3), blk>>>(x, DD, in_proj_w, DD, in_proj_b, nullptr, qkvb, 384, nullptr);
    attn_mma<<<NGR * NH, blk, ATTN_SMEM>>>(qkvb, ao);
    gemm_tf32<true, false, true, true><<<dim3(GB, 1), blk>>>(ao, DD, out_proj_w, DD, out_proj_b, x, ha, DD, stats_ha);

    // ---- local GINE branch ----
    gemm_tf32<false, true,  false, false><<<dim3(GB, 1), blk>>>(z,  DD, gin_w1, DD, gin_b1, nullptr, t1, DD, nullptr);
    gemm_tf32<false, false, true,  true ><<<dim3(GB, 1), blk>>>(t1, DD, gin_w2, DD, gin_b2, x,       hl, DD, stats_hl);

    // ---- combine: h = bn1a(ha) + bn1l(hl) ----
    bn_apply_dual<<<128, blk>>>(ha, stats_ha, bn1a_g, bn1a_b,
                                hl, stats_hl, bn1l_g, bn1l_b, h);

    // ---- FFN ----
    gemm_tf32<false, true,  false, false><<<dim3(GB, 2), blk>>>(h,  DD,     ff_w1, 2 * DD, ff_b1, nullptr, t1, 2 * DD, nullptr);
    gemm_tf32<false, false, true,  true ><<<dim3(GB, 1), blk>>>(t1, 2 * DD, ff_w2, DD,     ff_b2, h,       h2, DD, stats_h2);
    bn_apply_one<<<128, blk>>>(h2, stats_h2, bn2_g, bn2_b, out);
}

// round 4
// speedup vs baseline: 4.9086x; 1.0790x over previous
#include <cuda_runtime.h>
#include <math.h>
#include <stdint.h>

// Problem constants
constexpr int NN  = 16384;   // nodes
constexpr int DD  = 128;     // dim
constexpr int EE  = 262144;  // edges
constexpr int SEQ = 512;     // nodes per graph
constexpr int NGR = 32;      // graphs
constexpr int NH  = 8;       // heads (dh = 16)

// ---------------- scratch ----------------
__device__ float g_z   [NN * DD];
__device__ float g_hl  [NN * DD];
__device__ float g_qkv [NN * 3 * DD];
__device__ float g_ao  [NN * DD];
__device__ float g_ha  [NN * DD];
__device__ float g_h   [NN * DD];
__device__ float g_h2  [NN * DD];
__device__ float g_stats[768];   // [0:256) hl, [256:512) ha, [512:768) h2
__device__ int   g_deg [NN];
__device__ int   g_off [NN + 1];
__device__ int   g_pos [NN];
__device__ int   g_eid [EE];

// =====================================================================
__global__ void zero_misc(int* deg, float* stats)
{
    int i = blockIdx.x * 256 + threadIdx.x;
    deg[i] = 0;
    if (i < 768) stats[i] = 0.f;
}

// =====================================================================
// CSR build by dst:  count -> scan -> scatter
// =====================================================================
__global__ void count_kernel(const int* __restrict__ dst, int* __restrict__ deg)
{
    int e = blockIdx.x * 256 + threadIdx.x;
    atomicAdd(&deg[dst[e]], 1);
}

__global__ void __launch_bounds__(1024)
scan_kernel(const int* __restrict__ deg, int* __restrict__ off, int* __restrict__ pos)
{
    __shared__ int buf[2][1024];
    int t = threadIdx.x;
    int base = t * 16;
    int loc[16];
    int sum = 0;
#pragma unroll
    for (int i = 0; i < 16; ++i) { loc[i] = sum; sum += deg[base + i]; }
    buf[0][t] = sum;
    __syncthreads();
    int sel = 0;
    for (int d = 1; d < 1024; d <<= 1) {
        int v = buf[sel][t] + (t >= d ? buf[sel][t - d] : 0);
        buf[sel ^ 1][t] = v;
        sel ^= 1;
        __syncthreads();
    }
    int excl = buf[sel][t] - sum;
#pragma unroll
    for (int i = 0; i < 16; ++i) {
        int o = excl + loc[i];
        off[base + i] = o;
        pos[base + i] = o;
    }
    if (t == 1023) off[NN] = excl + sum;
}

__global__ void scatter_kernel(const int* __restrict__ dst, int* __restrict__ pos,
                               int* __restrict__ eid)
{
    int e = blockIdx.x * 256 + threadIdx.x;
    int p = atomicAdd(&pos[dst[e]], 1);
    eid[p] = e;
}

// =====================================================================
// Gather aggregation: z = x + sum_{e -> node} relu(x[src[e]] + ea[e])
// =====================================================================
__global__ void __launch_bounds__(256)
aggr_kernel(const float* __restrict__ x, const int* __restrict__ src,
            const float* __restrict__ ea, const int* __restrict__ off,
            const int* __restrict__ eid, float* __restrict__ z)
{
    int node = blockIdx.x * 8 + (threadIdx.x >> 5);
    int lane = threadIdx.x & 31;
    int beg = off[node], end = off[node + 1];
    const float4* x4  = (const float4*)x;
    const float4* ea4 = (const float4*)ea;
    float4 acc = make_float4(0.f, 0.f, 0.f, 0.f);
#pragma unroll 2
    for (int i = beg; i < end; ++i) {
        int e = __ldg(eid + i);
        int s = __ldg(src + e);
        float4 a = x4[(size_t)s * 32 + lane];
        float4 b = ea4[(size_t)e * 32 + lane];
        acc.x += fmaxf(a.x + b.x, 0.f);
        acc.y += fmaxf(a.y + b.y, 0.f);
        acc.z += fmaxf(a.z + b.z, 0.f);
        acc.w += fmaxf(a.w + b.w, 0.f);
    }
    float4 xv = x4[(size_t)node * 32 + lane];
    ((float4*)z)[(size_t)node * 32 + lane] =
        make_float4(xv.x + acc.x, xv.y + acc.y, xv.z + acc.z, xv.w + acc.w);
}

// =====================================================================
// TF32 mma helpers
// =====================================================================
__device__ __forceinline__ uint32_t to_tf32(float f)
{
    uint32_t u;
    asm("cvt.rna.tf32.f32 %0, %1;" : "=r"(u) : "f"(f));
    return u;
}

__device__ __forceinline__ void mma_tf32(float c[4], const uint32_t a[4], const uint32_t b[2])
{
    asm volatile(
        "mma.sync.aligned.m16n8k8.row.col.f32.tf32.tf32.f32 "
        "{%0,%1,%2,%3}, {%4,%5,%6,%7}, {%8,%9}, {%0,%1,%2,%3};\n"
        : "+f"(c[0]), "+f"(c[1]), "+f"(c[2]), "+f"(c[3])
        : "r"(a[0]), "r"(a[1]), "r"(a[2]), "r"(a[3]), "r"(b[0]), "r"(b[1]));
}

constexpr int AST = 132;   // A/T smem stride (u32)
constexpr int BST = 20;    // B-chunk smem stride

// one 16-k-slab of mma: A-src (stride AST), B-chunk (stride BST)
__device__ __forceinline__ void mma_slab16(const uint32_t* S, const uint32_t* Bb,
                                           float acc[4][4][4],
                                           int wm, int wn, int g, int tig, int kt)
{
#pragma unroll
    for (int k8s = 0; k8s < 2; ++k8s) {
        const int kk = kt * 16 + k8s * 8;
        uint32_t af[4][4];
#pragma unroll
        for (int mf = 0; mf < 4; ++mf) {
            const uint32_t* pa = S + (wm * 64 + mf * 16 + g) * AST + kk + tig;
            af[mf][0] = pa[0];
            af[mf][1] = pa[8 * AST];
            af[mf][2] = pa[4];
            af[mf][3] = pa[8 * AST + 4];
        }
        uint32_t bf[4][2];
#pragma unroll
        for (int nf = 0; nf < 4; ++nf) {
            const uint32_t* pb = Bb + (wn * 32 + nf * 8 + g) * BST + k8s * 8 + tig;
            bf[nf][0] = pb[0];
            bf[nf][1] = pb[4];
        }
#pragma unroll
        for (int mf = 0; mf < 4; ++mf)
#pragma unroll
            for (int nf = 0; nf < 4; ++nf)
                mma_tf32(acc[mf][nf], af[mf], bf[nf]);
    }
}

// epilogue shared by gemm_ar / mlp_fused
template<bool RELU, bool RESID, bool STATS>
__device__ __forceinline__ void gemm_epilogue(
    float acc[4][4][4], const float* bias, const float* resid,
    float* C, int ldc, int m0, int n0,
    int wm, int wn, int g, int tig, int tid,
    float* stats, float* sst /* 256-float smem scratch */)
{
    float cs[8], cq[8];
    if (STATS) {
#pragma unroll
        for (int j = 0; j < 8; ++j) { cs[j] = 0.f; cq[j] = 0.f; }
    }
#pragma unroll
    for (int mf = 0; mf < 4; ++mf) {
#pragma unroll
        for (int nf = 0; nf < 4; ++nf) {
            int row = m0 + wm * 64 + mf * 16 + g;
            int col = n0 + wn * 32 + nf * 8 + 2 * tig;
            float b0 = bias[col], b1 = bias[col + 1];
            float o00 = acc[mf][nf][0] + b0, o01 = acc[mf][nf][1] + b1;
            float o10 = acc[mf][nf][2] + b0, o11 = acc[mf][nf][3] + b1;
            if (RELU) {
                o00 = fmaxf(o00, 0.f); o01 = fmaxf(o01, 0.f);
                o10 = fmaxf(o10, 0.f); o11 = fmaxf(o11, 0.f);
            }
            if (RESID) {
                float2 r0 = *(const float2*)(resid + (size_t)row * ldc + col);
                float2 r1 = *(const float2*)(resid + (size_t)(row + 8) * ldc + col);
                o00 += r0.x; o01 += r0.y;
                o10 += r1.x; o11 += r1.y;
            }
            if (STATS) {
                cs[nf*2]   += o00 + o10;
                cs[nf*2+1] += o01 + o11;
                cq[nf*2]   += o00*o00 + o10*o10;
                cq[nf*2+1] += o01*o01 + o11*o11;
            }
            *(float2*)(C + (size_t)row * ldc + col)       = make_float2(o00, o01);
            *(float2*)(C + (size_t)(row + 8) * ldc + col) = make_float2(o10, o11);
        }
    }
    if (STATS) {
        __syncthreads();
        sst[tid] = 0.f;
        __syncthreads();
#pragma unroll
        for (int j = 0; j < 8; ++j) {
            int col = wn * 32 + (j >> 1) * 8 + 2 * tig + (j & 1);
            atomicAdd(&sst[col],       cs[j]);
            atomicAdd(&sst[128 + col], cq[j]);
        }
        __syncthreads();
        atomicAdd(&stats[tid], sst[tid]);
    }
}

// =====================================================================
// A-resident GEMM (K=128): C = A[128rows,128] @ B^T + bias (+resid)(+stats)
// B is [ncols, 128] row-major (torch W). Prefetch-pipelined B chunks.
// =====================================================================
constexpr int GEMM_AR_SMEM = (128 * AST + 128 * BST) * 4;

template<bool RESID, bool STATS>
__global__ void __launch_bounds__(256, 2)
gemm_ar(const float* __restrict__ A,
        const float* __restrict__ B,
        const float* __restrict__ bias,
        const float* __restrict__ resid,
        float* __restrict__ C, int ldc,
        float* __restrict__ stats)
{
    extern __shared__ uint32_t sm[];
    uint32_t* Abuf = sm;               // [128][AST]
    uint32_t* Bbuf = sm + 128 * AST;   // [128][BST]

    const int tid = threadIdx.x;
    const int lane = tid & 31, warp = tid >> 5;
    const int wm = warp >> 2, wn = warp & 3;
    const int g = lane >> 2, tig = lane & 3;
    const int m0 = blockIdx.x * 128;
    const int n0 = blockIdx.y * 128;

    // stage A strip (coalesced: warp loads one 512B row)
#pragma unroll
    for (int it = 0; it < 16; ++it) {
        int idx = tid + it * 256;
        int r = idx >> 5, c4 = (idx & 31) * 4;
        float4 v = *(const float4*)(A + (size_t)(m0 + r) * 128 + c4);
        uint32_t* d = Abuf + r * AST + c4;
        d[0] = to_tf32(v.x); d[1] = to_tf32(v.y);
        d[2] = to_tf32(v.z); d[3] = to_tf32(v.w);
    }

    float acc[4][4][4];
#pragma unroll
    for (int i = 0; i < 4; ++i)
#pragma unroll
        for (int j = 0; j < 4; ++j)
#pragma unroll
            for (int r = 0; r < 4; ++r) acc[i][j][r] = 0.f;

    // prefetch B chunk 0 (trans layout: row n, 16 k) : 2 float4 per thread
    float4 pre0, pre1;
    {
        int i0 = tid, i1 = tid + 256;
        pre0 = *(const float4*)(B + (size_t)(n0 + (i0 >> 2)) * 128 + (i0 & 3) * 4);
        pre1 = *(const float4*)(B + (size_t)(n0 + (i1 >> 2)) * 128 + (i1 & 3) * 4);
    }

    for (int kt = 0; kt < 8; ++kt) {
        __syncthreads();
        {
            int i0 = tid, i1 = tid + 256;
            uint32_t* d0 = Bbuf + (i0 >> 2) * BST + (i0 & 3) * 4;
            d0[0] = to_tf32(pre0.x); d0[1] = to_tf32(pre0.y);
            d0[2] = to_tf32(pre0.z); d0[3] = to_tf32(pre0.w);
            uint32_t* d1 = Bbuf + (i1 >> 2) * BST + (i1 & 3) * 4;
            d1[0] = to_tf32(pre1.x); d1[1] = to_tf32(pre1.y);
            d1[2] = to_tf32(pre1.z); d1[3] = to_tf32(pre1.w);
        }
        if (kt < 7) {
            int i0 = tid, i1 = tid + 256;
            pre0 = *(const float4*)(B + (size_t)(n0 + (i0 >> 2)) * 128 + (kt + 1) * 16 + (i0 & 3) * 4);
            pre1 = *(const float4*)(B + (size_t)(n0 + (i1 >> 2)) * 128 + (kt + 1) * 16 + (i1 & 3) * 4);
        }
        __syncthreads();
        mma_slab16(Abuf, Bbuf, acc, wm, wn, g, tig, kt);
    }

    gemm_epilogue<false, RESID, STATS>(acc, bias, resid, C, ldc, m0, n0,
                                       wm, wn, g, tig, tid, stats, (float*)Bbuf);
}

// =====================================================================
// Fused MLP: C = relu(A @ W1 + b1) @ W2 + b2 (+resid)(+stats)
// A: [128rows, 128]; W1: [128, NC*128] row-major; W2: [NC*128, 128] row-major.
// Hidden tile lives in smem (tf32), never touches gmem.
// =====================================================================
constexpr int MLP_SMEM = (2 * 128 * AST + 128 * BST) * 4;

template<int NC, bool STATS>
__global__ void __launch_bounds__(256, 1)
mlp_fused(const float* __restrict__ A,
          const float* __restrict__ W1, const float* __restrict__ b1,
          const float* __restrict__ W2, const float* __restrict__ b2,
          const float* __restrict__ resid,
          float* __restrict__ C,
          float* __restrict__ stats)
{
    extern __shared__ uint32_t sm[];
    uint32_t* Abuf = sm;                   // [128][AST]
    uint32_t* Tbuf = sm + 128 * AST;       // [128][AST]
    uint32_t* Bbuf = sm + 2 * 128 * AST;   // [128][BST]

    const int tid = threadIdx.x;
    const int lane = tid & 31, warp = tid >> 5;
    const int wm = warp >> 2, wn = warp & 3;
    const int g = lane >> 2, tig = lane & 3;
    const int m0 = blockIdx.x * 128;
    const int ldw1 = NC * 128;

    // stage A strip
#pragma unroll
    for (int it = 0; it < 16; ++it) {
        int idx = tid + it * 256;
        int r = idx >> 5, c4 = (idx & 31) * 4;
        float4 v = *(const float4*)(A + (size_t)(m0 + r) * 128 + c4);
        uint32_t* d = Abuf + r * AST + c4;
        d[0] = to_tf32(v.x); d[1] = to_tf32(v.y);
        d[2] = to_tf32(v.z); d[3] = to_tf32(v.w);
    }

    float co[4][4][4];
#pragma unroll
    for (int i = 0; i < 4; ++i)
#pragma unroll
        for (int j = 0; j < 4; ++j)
#pragma unroll
            for (int r = 0; r < 4; ++r) co[i][j][r] = 0.f;

    const int kk = tid >> 7;        // 0..1 (k within pair)
    const int nn2 = tid & 127;      // n col

#pragma unroll
    for (int nc = 0; nc < NC; ++nc) {
        // ================= phase 1: c1 = A @ W1[:, nc*128..] =================
        float c1[4][4][4];
#pragma unroll
        for (int i = 0; i < 4; ++i)
#pragma unroll
            for (int j = 0; j < 4; ++j)
#pragma unroll
                for (int r = 0; r < 4; ++r) c1[i][j][r] = 0.f;

        float pre[8];
#pragma unroll
        for (int j = 0; j < 8; ++j)  // chunk 0: k = j*2 + kk
            pre[j] = W1[(size_t)(j * 2 + kk) * ldw1 + nc * 128 + nn2];

        for (int kt = 0; kt < 8; ++kt) {
            __syncthreads();
#pragma unroll
            for (int j = 0; j < 8; ++j)
                Bbuf[nn2 * BST + j * 2 + kk] = to_tf32(pre[j]);
            if (kt < 7) {
#pragma unroll
                for (int j = 0; j < 8; ++j)
                    pre[j] = W1[(size_t)((kt + 1) * 16 + j * 2 + kk) * ldw1 + nc * 128 + nn2];
            }
            __syncthreads();
            mma_slab16(Abuf, Bbuf, c1, wm, wn, g, tig, kt);
        }

        // write hidden tile: relu(c1 + b1chunk) -> Tbuf (tf32)
#pragma unroll
        for (int mf = 0; mf < 4; ++mf) {
#pragma unroll
            for (int nf = 0; nf < 4; ++nf) {
                int row = wm * 64 + mf * 16 + g;
                int col = wn * 32 + nf * 8 + 2 * tig;
                float bb0 = b1[nc * 128 + col], bb1 = b1[nc * 128 + col + 1];
                Tbuf[row * AST + col]           = to_tf32(fmaxf(c1[mf][nf][0] + bb0, 0.f));
                Tbuf[row * AST + col + 1]       = to_tf32(fmaxf(c1[mf][nf][1] + bb1, 0.f));
                Tbuf[(row + 8) * AST + col]     = to_tf32(fmaxf(c1[mf][nf][2] + bb0, 0.f));
                Tbuf[(row + 8) * AST + col + 1] = to_tf32(fmaxf(c1[mf][nf][3] + bb1, 0.f));
            }
        }

        // ================= phase 2: co += T @ W2[nc*128.., :] =================
#pragma unroll
        for (int j = 0; j < 8; ++j)
            pre[j] = W2[(size_t)(nc * 128 + j * 2 + kk) * 128 + nn2];

        for (int kt = 0; kt < 8; ++kt) {
            __syncthreads();
#pragma unroll
            for (int j = 0; j < 8; ++j)
                Bbuf[nn2 * BST + j * 2 + kk] = to_tf32(pre[j]);
            if (kt < 7) {
#pragma unroll
                for (int j = 0; j < 8; ++j)
                    pre[j] = W2[(size_t)(nc * 128 + (kt + 1) * 16 + j * 2 + kk) * 128 + nn2];
            }
            __syncthreads();
            mma_slab16(Tbuf, Bbuf, co, wm, wn, g, tig, kt);
        }
    }

    gemm_epilogue<false, true, STATS>(co, b2, resid, C, 128, m0, 0,
                                      wm, wn, g, tig, tid, stats, (float*)Bbuf);
}

// =====================================================================
// Flash-style TF32 tensor-core attention (unchanged from R3).
// =====================================================================
constexpr int KS_STRIDE = 20;
constexpr int VS_STRIDE = 24;
constexpr int P_STRIDE  = 36;
constexpr int ATTN_SMEM = (512 * KS_STRIDE + 512 * VS_STRIDE + 8 * 64 * P_STRIDE) * 4;

__global__ void __launch_bounds__(256, 1)
attn_mma(const float* __restrict__ qkv, float* __restrict__ ao)
{
    extern __shared__ uint32_t sm[];
    uint32_t* Ks = sm;
    uint32_t* Vs = sm + 512 * KS_STRIDE;
    uint32_t* Pa = Vs + 512 * VS_STRIDE;

    const int tid  = threadIdx.x;
    const int lane = tid & 31;
    const int warp = tid >> 5;
    const int g    = lane >> 2;
    const int tig  = lane & 3;
    const int gi = blockIdx.x >> 3, h = blockIdx.x & 7;
    const float* base = qkv + (size_t)gi * SEQ * 384;

    uint32_t* Pw = Pa + warp * 64 * P_STRIDE;
    const int m0 = warp * 64;

    for (int idx = tid; idx < 2048; idx += 256) {
        int r = idx >> 2, c4 = (idx & 3) * 4;
        float4 kv = *(const float4*)(base + (size_t)r * 384 + 128 + h * 16 + c4);
        float4 vv = *(const float4*)(base + (size_t)r * 384 + 256 + h * 16 + c4);
        uint32_t* kd = Ks + r * KS_STRIDE + c4;
        kd[0] = to_tf32(kv.x); kd[1] = to_tf32(kv.y);
        kd[2] = to_tf32(kv.z); kd[3] = to_tf32(kv.w);
        uint32_t* vd = Vs + r * VS_STRIDE + c4;
        vd[0] = to_tf32(vv.x); vd[1] = to_tf32(vv.y);
        vd[2] = to_tf32(vv.z); vd[3] = to_tf32(vv.w);
    }
#pragma unroll
    for (int i = 0; i < 8; ++i) {
        int idx = lane + i * 32;
        int r = idx >> 2, c4 = (idx & 3) * 4;
        float4 qv = *(const float4*)(base + (size_t)(m0 + r) * 384 + h * 16 + c4);
        *(float4*)((float*)Pw + r * P_STRIDE + c4) = qv;
    }
    __syncthreads();

    uint32_t qa[4][2][4];
#pragma unroll
    for (int mt = 0; mt < 4; ++mt)
#pragma unroll
        for (int ks = 0; ks < 2; ++ks) {
            const float* p = (const float*)Pw + (mt * 16 + g) * P_STRIDE + ks * 8 + tig;
            qa[mt][ks][0] = to_tf32(p[0] * 0.25f);
            qa[mt][ks][1] = to_tf32(p[8 * P_STRIDE] * 0.25f);
            qa[mt][ks][2] = to_tf32(p[4] * 0.25f);
            qa[mt][ks][3] = to_tf32(p[8 * P_STRIDE + 4] * 0.25f);
        }
    __syncwarp();

    float o[4][2][4];
    float lrow[4][2];
#pragma unroll
    for (int mt = 0; mt < 4; ++mt) {
        lrow[mt][0] = 0.f; lrow[mt][1] = 0.f;
#pragma unroll
        for (int nt = 0; nt < 2; ++nt)
#pragma unroll
            for (int r = 0; r < 4; ++r) o[mt][nt][r] = 0.f;
    }

    for (int j = 0; j < 16; ++j) {
        const int n0 = j * 32;
        uint32_t bk[4][2][2];
#pragma unroll
        for (int nt = 0; nt < 4; ++nt)
#pragma unroll
            for (int ks = 0; ks < 2; ++ks) {
                const uint32_t* p = Ks + (n0 + nt * 8 + g) * KS_STRIDE + ks * 8 + tig;
                bk[nt][ks][0] = p[0];
                bk[nt][ks][1] = p[4];
            }
        float c[4][4][4];
#pragma unroll
        for (int mt = 0; mt < 4; ++mt)
#pragma unroll
            for (int nt = 0; nt < 4; ++nt) {
#pragma unroll
                for (int r = 0; r < 4; ++r) c[mt][nt][r] = 0.f;
                mma_tf32(c[mt][nt], qa[mt][0], bk[nt][0]);
                mma_tf32(c[mt][nt], qa[mt][1], bk[nt][1]);
            }
#pragma unroll
        for (int mt = 0; mt < 4; ++mt) {
#pragma unroll
            for (int nt = 0; nt < 4; ++nt) {
                float p0 = __expf(c[mt][nt][0]);
                float p1 = __expf(c[mt][nt][1]);
                float p2 = __expf(c[mt][nt][2]);
                float p3 = __expf(c[mt][nt][3]);
                lrow[mt][0] += p0 + p1;
                lrow[mt][1] += p2 + p3;
                uint32_t* d0 = Pw + (mt * 16 + g) * P_STRIDE + nt * 8 + 2 * tig;
                uint32_t* d1 = d0 + 8 * P_STRIDE;
                d0[0] = to_tf32(p0); d0[1] = to_tf32(p1);
                d1[0] = to_tf32(p2); d1[1] = to_tf32(p3);
            }
        }
        __syncwarp();
        uint32_t bv[4][2][2];
#pragma unroll
        for (int k2 = 0; k2 < 4; ++k2)
#pragma unroll
            for (int nt = 0; nt < 2; ++nt) {
                const uint32_t* p = Vs + (n0 + k2 * 8 + tig) * VS_STRIDE + nt * 8 + g;
                bv[k2][nt][0] = p[0];
                bv[k2][nt][1] = p[4 * VS_STRIDE];
            }
#pragma unroll
        for (int mt = 0; mt < 4; ++mt) {
#pragma unroll
            for (int k2 = 0; k2 < 4; ++k2) {
                uint32_t pa[4];
                const uint32_t* pp = Pw + (mt * 16 + g) * P_STRIDE + k2 * 8 + tig;
                pa[0] = pp[0];
                pa[1] = pp[8 * P_STRIDE];
                pa[2] = pp[4];
                pa[3] = pp[8 * P_STRIDE + 4];
                mma_tf32(o[mt][0], pa, bv[k2][0]);
                mma_tf32(o[mt][1], pa, bv[k2][1]);
            }
        }
        __syncwarp();
    }

#pragma unroll
    for (int mt = 0; mt < 4; ++mt) {
        float l0 = lrow[mt][0], l1 = lrow[mt][1];
        l0 += __shfl_xor_sync(0xffffffffu, l0, 1);
        l0 += __shfl_xor_sync(0xffffffffu, l0, 2);
        l1 += __shfl_xor_sync(0xffffffffu, l1, 1);
        l1 += __shfl_xor_sync(0xffffffffu, l1, 2);
        float i0 = 1.f / l0, i1 = 1.f / l1;
        int grow = gi * SEQ + m0 + mt * 16 + g;
#pragma unroll
        for (int nt = 0; nt < 2; ++nt) {
            int col = h * 16 + nt * 8 + 2 * tig;
            *(float2*)(ao + (size_t)grow * DD + col) =
                make_float2(o[mt][nt][0] * i0, o[mt][nt][1] * i0);
            *(float2*)(ao + (size_t)(grow + 8) * DD + col) =
                make_float2(o[mt][nt][2] * i1, o[mt][nt][3] * i1);
        }
    }
}

// =====================================================================
// BatchNorm applies
// =====================================================================
__device__ __forceinline__ void bn_coef(const float* stats, const float* gamma,
                                        const float* beta, int col,
                                        float& sc, float& sh)
{
    float mean = stats[col] * (1.f / (float)NN);
    float var  = stats[128 + col] * (1.f / (float)NN) - mean * mean;
    sc = gamma[col] * rsqrtf(var + 1e-5f);
    sh = beta[col] - mean * sc;
}

__global__ void __launch_bounds__(256)
bn_apply_one(const float* __restrict__ X, const float* __restrict__ stats,
             const float* __restrict__ gamma, const float* __restrict__ beta,
             float* __restrict__ out)
{
    int col = threadIdx.x & 127;
    int half = threadIdx.x >> 7;
    float sc, sh;
    bn_coef(stats, gamma, beta, col, sc, sh);
    int row0 = blockIdx.x * 128 + half * 64;
    size_t off = (size_t)row0 * DD + col;
#pragma unroll 4
    for (int r = 0; r < 64; ++r)
        out[off + r * DD] = X[off + r * DD] * sc + sh;
}

__global__ void __launch_bounds__(256)
bn_apply_dual(const float* __restrict__ ha, const float* __restrict__ statsA,
              const float* __restrict__ ga, const float* __restrict__ ba,
              const float* __restrict__ hl, const float* __restrict__ statsL,
              const float* __restrict__ gl, const float* __restrict__ bl,
              float* __restrict__ out)
{
    int col = threadIdx.x & 127;
    int half = threadIdx.x >> 7;
    float scA, shA, scL, shL;
    bn_coef(statsA, ga, ba, col, scA, shA);
    bn_coef(statsL, gl, bl, col, scL, shL);
    int row0 = blockIdx.x * 128 + half * 64;
    size_t off = (size_t)row0 * DD + col;
#pragma unroll 4
    for (int r = 0; r < 64; ++r)
        out[off + r * DD] = ha[off + r * DD] * scA + shA
                          + hl[off + r * DD] * scL + shL;
}

// =====================================================================
// Host launcher
// =====================================================================
extern "C" void kernel_launch(void* const* d_in, const int* in_sizes, int n_in,
                              void* d_out, int out_size)
{
    const float* x          = (const float*)d_in[0];
    const int*   edge_index = (const int*)  d_in[1];
    const float* edge_attr  = (const float*)d_in[2];
    const float* gin_w1     = (const float*)d_in[3];
    const float* gin_b1     = (const float*)d_in[4];
    const float* gin_w2     = (const float*)d_in[5];
    const float* gin_b2     = (const float*)d_in[6];
    const float* bn1l_g     = (const float*)d_in[7];
    const float* bn1l_b     = (const float*)d_in[8];
    const float* in_proj_w  = (const float*)d_in[9];
    const float* in_proj_b  = (const float*)d_in[10];
    const float* out_proj_w = (const float*)d_in[11];
    const float* out_proj_b = (const float*)d_in[12];
    const float* bn1a_g     = (const float*)d_in[13];
    const float* bn1a_b     = (const float*)d_in[14];
    const float* ff_w1      = (const float*)d_in[15];
    const float* ff_b1      = (const float*)d_in[16];
    const float* ff_w2      = (const float*)d_in[17];
    const float* ff_b2      = (const float*)d_in[18];
    const float* bn2_g      = (const float*)d_in[19];
    const float* bn2_b      = (const float*)d_in[20];
    float* out = (float*)d_out;

    cudaFuncSetAttribute(attn_mma, cudaFuncAttributeMaxDynamicSharedMemorySize, ATTN_SMEM);
    cudaFuncSetAttribute(gemm_ar<false, false>, cudaFuncAttributeMaxDynamicSharedMemorySize, GEMM_AR_SMEM);
    cudaFuncSetAttribute(gemm_ar<true,  true >, cudaFuncAttributeMaxDynamicSharedMemorySize, GEMM_AR_SMEM);
    cudaFuncSetAttribute(mlp_fused<1, true>, cudaFuncAttributeMaxDynamicSharedMemorySize, MLP_SMEM);
    cudaFuncSetAttribute(mlp_fused<2, true>, cudaFuncAttributeMaxDynamicSharedMemorySize, MLP_SMEM);

    float *z, *hl, *qkvb, *ao, *ha, *h, *h2, *stats;
    int *deg, *off, *pos, *eid;
    cudaGetSymbolAddress((void**)&z,    g_z);
    cudaGetSymbolAddress((void**)&hl,   g_hl);
    cudaGetSymbolAddress((void**)&qkvb, g_qkv);
    cudaGetSymbolAddress((void**)&ao,   g_ao);
    cudaGetSymbolAddress((void**)&ha,   g_ha);
    cudaGetSymbolAddress((void**)&h,    g_h);
    cudaGetSymbolAddress((void**)&h2,   g_h2);
    cudaGetSymbolAddress((void**)&stats, g_stats);
    cudaGetSymbolAddress((void**)&deg,  g_deg);
    cudaGetSymbolAddress((void**)&off,  g_off);
    cudaGetSymbolAddress((void**)&pos,  g_pos);
    cudaGetSymbolAddress((void**)&eid,  g_eid);

    const int* src = edge_index;
    const int* dst = edge_index + EE;
    const dim3 blk(256);
    const int GB = NN / 128;

    float* stats_hl = stats;
    float* stats_ha = stats + 256;
    float* stats_h2 = stats + 512;

    // launch order puts attn_mma at profile index 3
    zero_misc<<<64, blk>>>(deg, stats);                                            // 0
    gemm_ar<false, false><<<dim3(GB, 3), blk, GEMM_AR_SMEM>>>(x, in_proj_w, in_proj_b,
                                                              nullptr, qkvb, 384, nullptr);  // 1: QKV
    count_kernel<<<EE / 256, blk>>>(dst, deg);                                     // 2
    attn_mma<<<NGR * NH, blk, ATTN_SMEM>>>(qkvb, ao);                              // 3  <- profiled
    scan_kernel<<<1, 1024>>>(deg, off, pos);                                       // 4
    scatter_kernel<<<EE / 256, blk>>>(dst, pos, eid);                              // 5
    aggr_kernel<<<NN / 8, blk>>>(x, src, edge_attr, off, eid, z);                  // 6
    mlp_fused<1, true><<<GB, blk, MLP_SMEM>>>(z, gin_w1, gin_b1, gin_w2, gin_b2,
                                              x, hl, stats_hl);                    // 7: GINE MLP
    gemm_ar<true, true><<<dim3(GB, 1), blk, GEMM_AR_SMEM>>>(ao, out_proj_w, out_proj_b,
                                                            x, ha, 128, stats_ha); // 8: out_proj
    bn_apply_dual<<<128, blk>>>(ha, stats_ha, bn1a_g, bn1a_b,
                                hl, stats_hl, bn1l_g, bn1l_b, h);                  // 9
    mlp_fused<2, true><<<GB, blk, MLP_SMEM>>>(h, ff_w1, ff_b1, ff_w2, ff_b2,
                                              h, h2, stats_h2);                    // 10: FFN
    bn_apply_one<<<128, blk>>>(h2, stats_h2, bn2_g, bn2_b, out);                   // 11
}